// round 5
// baseline (speedup 1.0000x reference)
#include <cuda_runtime.h>

#define Bq   64
#define NPG  501
#define NN   (Bq * NPG)        // 32064
#define HID  128
#define LMD  1024
#define NREL 42
#define EMAX 520001
#define NPAD (NN + 128)
#define GB   148               // mega-kernel grid (1 block/SM, guaranteed co-resident)
#define GT   256

// ---------------- scratch (device globals; no allocs) ----------------
__device__ int   g_is64;
__device__ int   g_src[EMAX];
__device__ int   g_dst[EMAX];
__device__ int   g_etype[EMAX];
__device__ int   g_ctxn[Bq];
__device__ float g_ctx[Bq * HID];
__device__ float g_tdot[NREL];
__device__ float g_tmpT[Bq * HID * HID];      // [b][h][k]
__device__ float g_x[NPAD * HID];
__device__ float g_nodes[NPAD * HID];
__device__ float g_xl[NPAD * HID];
__device__ float g_as[NPAD];
__device__ float g_ad[NPAD];
__device__ float g_loop[NN];
__device__ int   g_deg[NN];
__device__ int   g_off[NN + 1];
__device__ int   g_pos[NN];
__device__ int   g_csrc[EMAX];
__device__ float g_cae[EMAX];
// active-set pruning
__device__ int   g_isctx[NN];
__device__ int   g_m3[NN];
__device__ int   g_m2[NN];
__device__ int   g_list2[NN];
__device__ int   g_list3[NN];
__device__ int   g_cnt2;
__device__ int   g_cnt3;
// software grid barrier (monotonic ticket counter; groups of GB arrivals)
__device__ volatile unsigned g_barcnt;

__device__ __forceinline__ void gsync() {
    __syncthreads();
    if (threadIdx.x == 0) {
        __threadfence();                                   // release + CCTL.IVALL
        unsigned t = atomicAdd((unsigned*)&g_barcnt, 1u);
        unsigned target = (t / GB + 1u) * GB;
        while (g_barcnt < target) { __nanosleep(64); }
        __threadfence();                                   // invalidate L1 (acquire)
    }
    __syncthreads();
}

// ============ MEGA: all graph/CSR/setup work in one kernel ============
__global__ void __launch_bounds__(GT) k_mega(
    const float* __restrict__ ne,
    const void* __restrict__ ei, const void* __restrict__ et,
    const void* __restrict__ ctxn,
    const float* __restrict__ We, const float* __restrict__ ae,
    const float* __restrict__ tab, int E)
{
    __shared__ float sv[HID];
    __shared__ int sp[GT];
    const int tid = threadIdx.x;
    const int gid = blockIdx.x * GT + tid;
    const int gstride = GB * GT;

    // ---------- Phase 0: init, x-copy, dtype flag, tdot prep ----------
    {
        const float4* s4 = (const float4*)ne;
        float4* d4 = (float4*)g_x;
        for (int j = gid; j < NN * HID / 4; j += gstride) d4[j] = s4[j];
        for (int j = gid; j < NN; j += gstride) {
            g_deg[j] = 0; g_isctx[j] = 0; g_m3[j] = 0; g_m2[j] = 0;
        }
        if (blockIdx.x == 0 && tid == 0) {
            g_is64 = (((const int*)ctxn)[1] == 0) ? 1 : 0;
            g_cnt2 = 0; g_cnt3 = 0;
        }
        if (blockIdx.x == 1) {   // v_edge = W_edge@att_edge; table_dot
            if (tid < HID) {
                float acc = 0.f;
                for (int j = 0; j < HID; j++) acc += We[tid * HID + j] * ae[j];
                sv[tid] = acc;
            }
            __syncthreads();
            if (tid < NREL) {
                float a2 = 0.f;
                for (int j = 0; j < HID; j++) a2 += tab[tid * HID + j] * sv[j];
                g_tdot[tid] = a2;
            }
        }
    }
    gsync();

    // ---------- Phase 1: cvt + deg atomics + ctx marks ----------
    {
        bool is64 = (g_is64 != 0);
        for (int i = gid; i < E; i += gstride) {
            int s, d, t;
            if (is64) {
                s = (int)((const long long*)ei)[i];
                d = (int)((const long long*)ei)[E + i];
                t = (int)((const long long*)et)[i];
            } else {
                s = ((const int*)ei)[i];
                d = ((const int*)ei)[E + i];
                t = ((const int*)et)[i];
            }
            g_src[i] = s; g_dst[i] = d; g_etype[i] = t;
            atomicAdd(&g_deg[d], 1);
        }
        if (gid < Bq) {
            int n = is64 ? (int)((const long long*)ctxn)[gid] : ((const int*)ctxn)[gid];
            g_ctxn[gid] = n;
            g_isctx[n] = 1;
            g_m3[n] = 1;
        }
    }
    gsync();

    // ---------- Phase 2: block 0 scans deg->off/pos; others mark3 ----------
    if (blockIdx.x == 0) {
        const int CH = (NN + GT - 1) / GT;   // 126
        int base = tid * CH;
        int s = 0;
        for (int i = 0; i < CH; i++) {
            int idx = base + i;
            if (idx < NN) s += g_deg[idx];
        }
        sp[tid] = s;
        __syncthreads();
        for (int d = 1; d < GT; d <<= 1) {
            int v = (tid >= d) ? sp[tid - d] : 0;
            __syncthreads();
            sp[tid] += v;
            __syncthreads();
        }
        int run = (tid == 0) ? 0 : sp[tid - 1];
        for (int i = 0; i < CH; i++) {
            int idx = base + i;
            if (idx < NN) {
                g_off[idx] = run; g_pos[idx] = run;
                run += g_deg[idx];
            }
        }
        if (tid == GT - 1) g_off[NN] = sp[GT - 1];
    } else {
        for (int i = (blockIdx.x - 1) * GT + tid; i < E; i += (GB - 1) * GT)
            if (g_isctx[g_dst[i]]) g_m3[g_src[i]] = 1;
    }
    gsync();

    // ---------- Phase 3: mark2 (blocks 0..73) ∥ CSR fill (blocks 74..147) ----------
    if (blockIdx.x < 74) {
        for (int i = blockIdx.x * GT + tid; i < E; i += 74 * GT)
            if (g_m3[g_dst[i]]) g_m2[g_src[i]] = 1;
    } else {
        for (int i = (blockIdx.x - 74) * GT + tid; i < E; i += 74 * GT) {
            int d = g_dst[i];
            int p = atomicAdd(&g_pos[d], 1);
            g_csrc[p] = g_src[i];
            g_cae[p] = g_tdot[g_etype[i]];
        }
    }
    gsync();

    // ---------- Phase 4: compact lists + self-loop means ----------
    {
        for (int n = gid; n < NN; n += gstride) {
            int in3 = g_m3[n];
            int in2 = g_m2[n] | in3;
            if (in3) g_list3[atomicAdd(&g_cnt3, 1)] = n;
            if (in2) g_list2[atomicAdd(&g_cnt2, 1)] = n;
        }
        int lane = tid & 31;
        int gwarp = gid >> 5;
        for (int w = gwarp; w < NN; w += GB * (GT / 32)) {
            int s = g_off[w], e = g_off[w + 1];
            float acc = 0.f;
            for (int i = s + lane; i < e; i += 32) acc += g_cae[i];
            for (int o = 16; o; o >>= 1) acc += __shfl_xor_sync(0xffffffffu, acc, o);
            if (lane == 0) {
                int d = e - s;
                g_loop[w] = d ? acc / (float)d : 0.f;
            }
        }
    }
}

// ctx_emb = lm @ W_lm + b_lm ; also writes ctx rows of g_x directly
__global__ void __launch_bounds__(1024) k_ctx(const float* __restrict__ lm,
                                              const float* __restrict__ W,
                                              const float* __restrict__ bl) {
    __shared__ float red[1024];
    int b = blockIdx.x, t = threadIdx.x;
    int c = t & 127, lg = t >> 7;
    const float* l0 = lm + (size_t)b * LMD + lg * 128;
    const float* Wp = W + (size_t)(lg * 128) * HID + c;
    float a0 = 0.f, a1 = 0.f;
#pragma unroll 8
    for (int l = 0; l < 128; l += 2) {
        a0 += l0[l] * Wp[(size_t)l * HID];
        a1 += l0[l + 1] * Wp[(size_t)(l + 1) * HID];
    }
    red[t] = a0 + a1;
    __syncthreads();
    for (int s = 512; s >= 128; s >>= 1) {
        if (t < s) red[t] += red[t + s];
        __syncthreads();
    }
    if (t < 128) {
        float v = red[t] + bl[t];
        g_ctx[b * HID + t] = v;
        g_x[(size_t)g_ctxn[b] * HID + t] = v;
    }
}

// tmpT[b][h][k] = sum_l lm[b,l]*W_bil[k,l,h]  — one block per k
__global__ void __launch_bounds__(256) k_tmp(const float* __restrict__ lm,
                                             const float* __restrict__ Wb) {
    int k = blockIdx.x;
    int t = threadIdx.x;
    int bg = t >> 4, hg = t & 15;
    int b0 = bg * 4, h0 = hg * 8;
    const float* Wk = Wb + (size_t)k * LMD * HID;
    float acc[4][8];
#pragma unroll
    for (int i = 0; i < 4; i++)
#pragma unroll
        for (int j = 0; j < 8; j++) acc[i][j] = 0.f;

    for (int l = 0; l < LMD; l += 4) {
        float a[4][4];
#pragma unroll
        for (int i = 0; i < 4; i++) {
            float4 v = *(const float4*)&lm[(size_t)(b0 + i) * LMD + l];
            a[i][0] = v.x; a[i][1] = v.y; a[i][2] = v.z; a[i][3] = v.w;
        }
#pragma unroll
        for (int u = 0; u < 4; u++) {
            float4 w0 = *(const float4*)&Wk[(size_t)(l + u) * HID + h0];
            float4 w1 = *(const float4*)&Wk[(size_t)(l + u) * HID + h0 + 4];
            float wr[8] = {w0.x, w0.y, w0.z, w0.w, w1.x, w1.y, w1.z, w1.w};
#pragma unroll
            for (int i = 0; i < 4; i++) {
                float av = a[i][u];
#pragma unroll
                for (int j = 0; j < 8; j++) acc[i][j] += av * wr[j];
            }
        }
    }
#pragma unroll
    for (int i = 0; i < 4; i++)
#pragma unroll
        for (int j = 0; j < 8; j++)
            g_tmpT[(size_t)(b0 + i) * HID * HID + (size_t)(h0 + j) * HID + k] = acc[i][j];
}

// full GEMM: mode 0: nodes0 per-graph; mode 1: xl = nodes@W_gat (+att dots)
__global__ void __launch_bounds__(256) k_gemm(int mode, const float* __restrict__ Bext,
                                              int M, int sA,
                                              const float* __restrict__ bias,
                                              const float* __restrict__ atts,
                                              const float* __restrict__ attd) {
    const float* A = mode ? g_nodes : g_x;
    float* C = mode ? g_xl : g_nodes;
    const float* Bm = mode ? Bext : (g_tmpT + (size_t)blockIdx.y * HID * HID);
    A += (size_t)blockIdx.y * sA;
    C += (size_t)blockIdx.y * sA;

    int t = threadIdx.x;
    int rg = t >> 3, cg = t & 7;
    int m0 = blockIdx.x * 128 + rg * 4;
    int k0 = cg * 16;

    float acc[4][16];
#pragma unroll
    for (int i = 0; i < 4; i++)
#pragma unroll
        for (int j = 0; j < 16; j++) acc[i][j] = 0.f;

    for (int h = 0; h < HID; h += 4) {
        float a[4][4];
#pragma unroll
        for (int i = 0; i < 4; i++) {
            float4 v = *(const float4*)&A[(size_t)(m0 + i) * HID + h];
            a[i][0] = v.x; a[i][1] = v.y; a[i][2] = v.z; a[i][3] = v.w;
        }
#pragma unroll
        for (int u = 0; u < 4; u++) {
            float br[16];
#pragma unroll
            for (int q = 0; q < 4; q++) {
                float4 w = *(const float4*)&Bm[(size_t)(h + u) * HID + k0 + q * 4];
                br[q * 4 + 0] = w.x; br[q * 4 + 1] = w.y;
                br[q * 4 + 2] = w.z; br[q * 4 + 3] = w.w;
            }
#pragma unroll
            for (int i = 0; i < 4; i++) {
                float av = a[i][u];
#pragma unroll
                for (int j = 0; j < 16; j++) acc[i][j] += av * br[j];
            }
        }
    }

    float bs[16];
    if (bias) {
#pragma unroll
        for (int q = 0; q < 4; q++) {
            float4 w = *(const float4*)&bias[k0 + q * 4];
            bs[q * 4 + 0] = w.x; bs[q * 4 + 1] = w.y;
            bs[q * 4 + 2] = w.z; bs[q * 4 + 3] = w.w;
        }
    } else {
#pragma unroll
        for (int j = 0; j < 16; j++) bs[j] = 0.f;
    }

#pragma unroll
    for (int i = 0; i < 4; i++) {
        int m = m0 + i;
        if (m < M) {
#pragma unroll
            for (int q = 0; q < 4; q++) {
                float4 w;
                w.x = acc[i][q * 4 + 0] + bs[q * 4 + 0];
                w.y = acc[i][q * 4 + 1] + bs[q * 4 + 1];
                w.z = acc[i][q * 4 + 2] + bs[q * 4 + 2];
                w.w = acc[i][q * 4 + 3] + bs[q * 4 + 3];
                *(float4*)&C[(size_t)m * HID + k0 + q * 4] = w;
            }
        }
    }

    if (atts) {
        float sa[16], da[16];
#pragma unroll
        for (int q = 0; q < 4; q++) {
            float4 w = *(const float4*)&atts[k0 + q * 4];
            sa[q * 4] = w.x; sa[q * 4 + 1] = w.y; sa[q * 4 + 2] = w.z; sa[q * 4 + 3] = w.w;
            float4 u = *(const float4*)&attd[k0 + q * 4];
            da[q * 4] = u.x; da[q * 4 + 1] = u.y; da[q * 4 + 2] = u.z; da[q * 4 + 3] = u.w;
        }
#pragma unroll
        for (int i = 0; i < 4; i++) {
            float ps = 0.f, pd = 0.f;
#pragma unroll
            for (int j = 0; j < 16; j++) {
                ps += acc[i][j] * sa[j];
                pd += acc[i][j] * da[j];
            }
            for (int o = 4; o; o >>= 1) {
                ps += __shfl_down_sync(0xffffffffu, ps, o, 8);
                pd += __shfl_down_sync(0xffffffffu, pd, o, 8);
            }
            int m = m0 + i;
            if (cg == 0 && m < M) { g_as[m] = ps; g_ad[m] = pd; }
        }
    }
}

// 32-row list-indirected GEMM: 1 row/thread-group-of-8, 16 cols each
__global__ void __launch_bounds__(256) k_gemml(int lsel, const float* __restrict__ Bm,
                                               const float* __restrict__ atts,
                                               const float* __restrict__ attd) {
    int cnt = lsel ? g_cnt3 : g_cnt2;
    if (blockIdx.x * 32 >= cnt) return;
    const int* list = lsel ? g_list3 : g_list2;

    int t = threadIdx.x;
    int rg = t >> 3, cg = t & 7;
    int m = blockIdx.x * 32 + rg;
    int k0 = cg * 16;

    bool ok = m < cnt;
    int row = ok ? list[m] : list[0];

    float acc[16];
#pragma unroll
    for (int j = 0; j < 16; j++) acc[j] = 0.f;

    for (int h = 0; h < HID; h += 4) {
        float4 v = *(const float4*)&g_nodes[(size_t)row * HID + h];
        float a[4] = {v.x, v.y, v.z, v.w};
#pragma unroll
        for (int u = 0; u < 4; u++) {
            float br[16];
#pragma unroll
            for (int q = 0; q < 4; q++) {
                float4 w = *(const float4*)&Bm[(size_t)(h + u) * HID + k0 + q * 4];
                br[q * 4 + 0] = w.x; br[q * 4 + 1] = w.y;
                br[q * 4 + 2] = w.z; br[q * 4 + 3] = w.w;
            }
            float av = a[u];
#pragma unroll
            for (int j = 0; j < 16; j++) acc[j] += av * br[j];
        }
    }

    if (ok) {
#pragma unroll
        for (int q = 0; q < 4; q++) {
            float4 w;
            w.x = acc[q * 4 + 0]; w.y = acc[q * 4 + 1];
            w.z = acc[q * 4 + 2]; w.w = acc[q * 4 + 3];
            *(float4*)&g_xl[(size_t)row * HID + k0 + q * 4] = w;
        }
    }

    float ps = 0.f, pd = 0.f;
#pragma unroll
    for (int q = 0; q < 4; q++) {
        float4 w = *(const float4*)&atts[k0 + q * 4];
        float4 u = *(const float4*)&attd[k0 + q * 4];
        ps += acc[q * 4 + 0] * w.x + acc[q * 4 + 1] * w.y + acc[q * 4 + 2] * w.z + acc[q * 4 + 3] * w.w;
        pd += acc[q * 4 + 0] * u.x + acc[q * 4 + 1] * u.y + acc[q * 4 + 2] * u.z + acc[q * 4 + 3] * u.w;
    }
    for (int o = 4; o; o >>= 1) {
        ps += __shfl_down_sync(0xffffffffu, ps, o, 8);
        pd += __shfl_down_sync(0xffffffffu, pd, o, 8);
    }
    if (cg == 0 && ok) { g_as[row] = ps; g_ad[row] = pd; }
}

// restricted softmax-aggregation: dst from list (0=list2, 1=list3, 2=ctx[+out])
__global__ void k_hopl(int lsel, const float* __restrict__ gbias,
                       float* __restrict__ out) {
    int wi = (blockIdx.x * blockDim.x + threadIdx.x) >> 5;
    int lane = threadIdx.x & 31;
    int cnt = (lsel == 0) ? g_cnt2 : (lsel == 1) ? g_cnt3 : Bq;
    if (wi >= cnt) return;
    int w = (lsel == 0) ? g_list2[wi] : (lsel == 1) ? g_list3[wi] : g_ctxn[wi];

    int s = g_off[w], e = g_off[w + 1];
    float adn = g_ad[w];
    float aself = g_as[w] + adn + g_loop[w];
    aself = aself >= 0.f ? aself : 0.2f * aself;
    float m = aself;
    for (int i = s + lane; i < e; i += 32) {
        float a = g_as[g_csrc[i]] + adn + g_cae[i];
        a = a >= 0.f ? a : 0.2f * a;
        m = fmaxf(m, a);
    }
    for (int o = 16; o; o >>= 1) m = fmaxf(m, __shfl_xor_sync(0xffffffffu, m, o));

    float eself = __expf(aself - m);
    float s_sum = eself;
    float4 v = ((const float4*)&g_xl[(size_t)w * HID])[lane];
    float4 acc;
    acc.x = eself * v.x; acc.y = eself * v.y; acc.z = eself * v.z; acc.w = eself * v.w;

    for (int i = s; i < e; i++) {
        int src = g_csrc[i];
        float a = g_as[src] + adn + g_cae[i];
        a = a >= 0.f ? a : 0.2f * a;
        float ee = __expf(a - m);
        s_sum += ee;
        float4 u = ((const float4*)&g_xl[(size_t)src * HID])[lane];
        acc.x += ee * u.x; acc.y += ee * u.y; acc.z += ee * u.z; acc.w += ee * u.w;
    }
    float inv = 1.f / s_sum;
    float4 bb = ((const float4*)gbias)[lane];
    float4 o;
    o.x = acc.x * inv + bb.x; o.y = acc.y * inv + bb.y;
    o.z = acc.z * inv + bb.z; o.w = acc.w * inv + bb.w;
    ((float4*)&g_nodes[(size_t)w * HID])[lane] = o;
    if (lsel == 2) ((float4*)&out[(size_t)wi * HID])[lane] = o;
}

extern "C" void kernel_launch(void* const* d_in, const int* in_sizes, int n_in,
                              void* d_out, int out_size) {
    const float* lm    = (const float*)d_in[0];
    const float* ne    = (const float*)d_in[1];
    const void*  ei    = d_in[2];
    const void*  et    = d_in[3];
    const void*  ctxn  = d_in[4];
    const float* Wlm  = (const float*)d_in[5];
    const float* blm  = (const float*)d_in[6];
    const float* Wbil = (const float*)d_in[7];
    const float* bbil = (const float*)d_in[8];
    const float* tab  = (const float*)d_in[9];
    const float* Wgat = (const float*)d_in[10];
    const float* atts = (const float*)d_in[11];
    const float* attd = (const float*)d_in[12];
    const float* Wed  = (const float*)d_in[13];
    const float* atte = (const float*)d_in[14];
    const float* gb   = (const float*)d_in[15];
    float* out = (float*)d_out;

    int E = in_sizes[2] / 2;
    int nb128 = (NN + 127) / 128;      // 128-row GEMM blocks
    int nb32  = (NN + 31) / 32;        // 32-row list-GEMM blocks (early exit)
    int wb = (NN + 7) / 8;             // warp-per-node blocks

    // 1) all setup/CSR/pruning in one fused kernel
    k_mega<<<GB, GT>>>(ne, ei, et, ctxn, Wed, atte, tab, E);
    // 2) ctx embedding (writes g_ctx and ctx rows of g_x)
    k_ctx<<<Bq, 1024>>>(lm, Wlm, blm);
    // 3) bilinear weight transform
    k_tmp<<<HID, 256>>>(lm, Wbil);
    // 4) nodes0: per-graph  xg @ tmp[b]^T + b_bil
    dim3 g0((NPG + 127) / 128, Bq);
    k_gemm<<<g0, 256>>>(0, nullptr, NPG, NPG * HID, bbil, nullptr, nullptr);
    // 5-6) hop 1: full GEMM, aggregate at A2
    k_gemm<<<dim3(nb128, 1), 256>>>(1, Wgat, NN, 0, nullptr, atts, attd);
    k_hopl<<<wb, 256>>>(0, gb, nullptr);
    // 7-8) hop 2: GEMM over A2, aggregate at A3
    k_gemml<<<nb32, 256>>>(0, Wgat, atts, attd);
    k_hopl<<<wb, 256>>>(1, gb, nullptr);
    // 9-10) hop 3: GEMM over A3, aggregate at ctx (+ write output)
    k_gemml<<<nb32, 256>>>(1, Wgat, atts, attd);
    k_hopl<<<(Bq + 7) / 8, 256>>>(2, gb, out);
}

// round 6
// speedup vs baseline: 1.1753x; 1.1753x over previous
#include <cuda_runtime.h>

#define Bq   64
#define NPG  501
#define NN   (Bq * NPG)        // 32064
#define HID  128
#define LMD  1024
#define NREL 42
#define EMAX 520001
#define NPAD (NN + 128)

// ---------------- scratch (device globals; no allocs) ----------------
__device__ int   g_src[EMAX];
__device__ int   g_dst[EMAX];
__device__ int   g_etype[EMAX];
__device__ int   g_ctxn[Bq];
__device__ float g_ctx[Bq * HID];
__device__ float g_tdot[NREL];
__device__ float g_tmpT[Bq * HID * HID];      // [b][h][k]
__device__ float g_x[NPAD * HID];
__device__ float g_nodes[NPAD * HID];
__device__ float g_xl[NPAD * HID];
__device__ float g_as[NPAD];
__device__ float g_ad[NPAD];
__device__ float g_loop[NN];
__device__ int   g_deg[NN];
__device__ int   g_off[NN + 1];
__device__ int   g_pos[NN];
__device__ int   g_csrc[EMAX];
__device__ float g_cae[EMAX];
// active-set pruning
__device__ int   g_isctx[NN];
__device__ int   g_m3[NN];
__device__ int   g_m2[NN];
__device__ int   g_list2[NN];
__device__ int   g_list3[NN];
__device__ int   g_cnt2;
__device__ int   g_cnt3;

// zero scratch + copy node_emb -> g_x (vectorized)
__global__ void k_init(const float* __restrict__ ne) {
    int i = blockIdx.x * blockDim.x + threadIdx.x;
    int stride = gridDim.x * blockDim.x;
    const float4* s4 = (const float4*)ne;
    float4* d4 = (float4*)g_x;
    for (int j = i; j < NN * HID / 4; j += stride) d4[j] = s4[j];
    for (int j = i; j < NN; j += stride) {
        g_deg[j] = 0; g_isctx[j] = 0; g_m3[j] = 0; g_m2[j] = 0;
    }
    if (i == 0) { g_cnt2 = 0; g_cnt3 = 0; }
}

// cvt (dtype-flexible) + degree atomics + ctx marks, all in one pass
__global__ void k_cvt(const void* __restrict__ ei, const void* __restrict__ et,
                      const void* __restrict__ ctxn, int E) {
    int i = blockIdx.x * blockDim.x + threadIdx.x;
    // int64 layout -> word #1 is high word of ctx_nodes[0]==0; int32 -> 501
    bool is64 = (((const int*)ctxn)[1] == 0);
    if (i < E) {
        int s, d, t;
        if (is64) {
            s = (int)((const long long*)ei)[i];
            d = (int)((const long long*)ei)[E + i];
            t = (int)((const long long*)et)[i];
        } else {
            s = ((const int*)ei)[i];
            d = ((const int*)ei)[E + i];
            t = ((const int*)et)[i];
        }
        g_src[i] = s; g_dst[i] = d; g_etype[i] = t;
        atomicAdd(&g_deg[d], 1);
    }
    if (i < Bq) {
        int n = is64 ? (int)((const long long*)ctxn)[i] : ((const int*)ctxn)[i];
        g_ctxn[i] = n;
        g_isctx[n] = 1;
        g_m3[n] = 1;
    }
}

// v_edge = W_edge@att_edge; table_dot (MUST precede k_fill)
__global__ void k_prep(const float* __restrict__ We, const float* __restrict__ ae,
                       const float* __restrict__ tab) {
    __shared__ float sv[HID];
    int t = threadIdx.x;
    float acc = 0.f;
    for (int j = 0; j < HID; j++) acc += We[t * HID + j] * ae[j];
    sv[t] = acc;
    __syncthreads();
    if (t < NREL) {
        float a2 = 0.f;
        for (int j = 0; j < HID; j++) a2 += tab[t * HID + j] * sv[j];
        g_tdot[t] = a2;
    }
}

__global__ void k_mark3(int E) {
    int i = blockIdx.x * blockDim.x + threadIdx.x;
    if (i < E && g_isctx[g_dst[i]]) g_m3[g_src[i]] = 1;
}

__global__ void k_mark2(int E) {
    int i = blockIdx.x * blockDim.x + threadIdx.x;
    if (i < E && g_m3[g_dst[i]]) g_m2[g_src[i]] = 1;
}

// single-block exclusive scan over g_deg -> g_off, g_pos
__global__ void k_scan() {
    __shared__ int sp[1024];
    int t = threadIdx.x;
    int base = t * 32;
    int loc[32];
    int s = 0;
#pragma unroll
    for (int i = 0; i < 32; i++) {
        int idx = base + i;
        int v = (idx < NN) ? g_deg[idx] : 0;
        loc[i] = s;
        s += v;
    }
    sp[t] = s;
    __syncthreads();
    for (int d = 1; d < 1024; d <<= 1) {
        int v = (t >= d) ? sp[t - d] : 0;
        __syncthreads();
        sp[t] += v;
        __syncthreads();
    }
    int chunk = (t == 0) ? 0 : sp[t - 1];
#pragma unroll
    for (int i = 0; i < 32; i++) {
        int idx = base + i;
        if (idx < NN) {
            int o = chunk + loc[i];
            g_off[idx] = o;
            g_pos[idx] = o;
        }
    }
    if (t == 1023) g_off[NN] = sp[1023];
}

__global__ void k_fill(int E) {
    int i = blockIdx.x * blockDim.x + threadIdx.x;
    if (i < E) {
        int d = g_dst[i];
        int p = atomicAdd(&g_pos[d], 1);
        g_csrc[p] = g_src[i];
        g_cae[p] = g_tdot[g_etype[i]];
    }
}

__global__ void k_compact() {
    int n = blockIdx.x * blockDim.x + threadIdx.x;
    if (n >= NN) return;
    int in3 = g_m3[n];
    int in2 = g_m2[n] | in3;
    if (in3) g_list3[atomicAdd(&g_cnt3, 1)] = n;
    if (in2) g_list2[atomicAdd(&g_cnt2, 1)] = n;
}

// self-loop attention bias = mean of incoming table_dot
__global__ void k_loopdot() {
    int w = (blockIdx.x * blockDim.x + threadIdx.x) >> 5;
    int lane = threadIdx.x & 31;
    if (w >= NN) return;
    int s = g_off[w], e = g_off[w + 1];
    float acc = 0.f;
    for (int i = s + lane; i < e; i += 32) acc += g_cae[i];
    for (int o = 16; o; o >>= 1) acc += __shfl_xor_sync(0xffffffffu, acc, o);
    if (lane == 0) {
        int d = e - s;
        g_loop[w] = d ? acc / (float)d : 0.f;
    }
}

// ctx_emb = lm @ W_lm + b_lm ; writes g_ctx and ctx rows of g_x
__global__ void __launch_bounds__(1024) k_ctx(const float* __restrict__ lm,
                                              const float* __restrict__ W,
                                              const float* __restrict__ bl) {
    __shared__ float red[1024];
    int b = blockIdx.x, t = threadIdx.x;
    int c = t & 127, lg = t >> 7;
    const float* l0 = lm + (size_t)b * LMD + lg * 128;
    const float* Wp = W + (size_t)(lg * 128) * HID + c;
    float a0 = 0.f, a1 = 0.f;
#pragma unroll 8
    for (int l = 0; l < 128; l += 2) {
        a0 += l0[l] * Wp[(size_t)l * HID];
        a1 += l0[l + 1] * Wp[(size_t)(l + 1) * HID];
    }
    red[t] = a0 + a1;
    __syncthreads();
    for (int s = 512; s >= 128; s >>= 1) {
        if (t < s) red[t] += red[t + s];
        __syncthreads();
    }
    if (t < 128) {
        float v = red[t] + bl[t];
        g_ctx[b * HID + t] = v;
        g_x[(size_t)g_ctxn[b] * HID + t] = v;
    }
}

// tmpT[b][h][k] = sum_l lm[b,l]*W_bil[k,l,h]  — one block per k
__global__ void __launch_bounds__(256) k_tmp(const float* __restrict__ lm,
                                             const float* __restrict__ Wb) {
    int k = blockIdx.x;
    int t = threadIdx.x;
    int bg = t >> 4, hg = t & 15;
    int b0 = bg * 4, h0 = hg * 8;
    const float* Wk = Wb + (size_t)k * LMD * HID;
    float acc[4][8];
#pragma unroll
    for (int i = 0; i < 4; i++)
#pragma unroll
        for (int j = 0; j < 8; j++) acc[i][j] = 0.f;

    for (int l = 0; l < LMD; l += 4) {
        float a[4][4];
#pragma unroll
        for (int i = 0; i < 4; i++) {
            float4 v = *(const float4*)&lm[(size_t)(b0 + i) * LMD + l];
            a[i][0] = v.x; a[i][1] = v.y; a[i][2] = v.z; a[i][3] = v.w;
        }
#pragma unroll
        for (int u = 0; u < 4; u++) {
            float4 w0 = *(const float4*)&Wk[(size_t)(l + u) * HID + h0];
            float4 w1 = *(const float4*)&Wk[(size_t)(l + u) * HID + h0 + 4];
            float wr[8] = {w0.x, w0.y, w0.z, w0.w, w1.x, w1.y, w1.z, w1.w};
#pragma unroll
            for (int i = 0; i < 4; i++) {
                float av = a[i][u];
#pragma unroll
                for (int j = 0; j < 8; j++) acc[i][j] += av * wr[j];
            }
        }
    }
#pragma unroll
    for (int i = 0; i < 4; i++)
#pragma unroll
        for (int j = 0; j < 8; j++)
            g_tmpT[(size_t)(b0 + i) * HID * HID + (size_t)(h0 + j) * HID + k] = acc[i][j];
}

// ===== smem-staged 128x128 GEMM, 8x8 register tile / thread =====
// mode 0: A=g_x(+b*NPG*HID), B=g_tmpT[b], C=g_nodes(+...), +bias
// mode 1: A=g_nodes, B=Bext(W_gat), C=g_xl, + att_src/att_dst row dots
__global__ void __launch_bounds__(256, 2) k_gemm2(int mode, const float* __restrict__ Bext,
                                                  int M, int sA,
                                                  const float* __restrict__ bias,
                                                  const float* __restrict__ atts,
                                                  const float* __restrict__ attd) {
    __shared__ float Bs[64 * 128];      // 32 KB, staged in 2 chunks of K
    const float* A = mode ? g_nodes : g_x;
    float* C = mode ? g_xl : g_nodes;
    const float* Bm = mode ? Bext : (g_tmpT + (size_t)blockIdx.y * HID * HID);
    A += (size_t)blockIdx.y * sA;
    C += (size_t)blockIdx.y * sA;

    const int t = threadIdx.x;
    const int tc = t & 15, tr = t >> 4;
    const int r0 = blockIdx.x * 128 + tr * 8;   // 8 consecutive rows
    const int c0 = tc * 4;                      // cols c0..c0+3 and c0+64..c0+67

    float acc[8][8];
#pragma unroll
    for (int i = 0; i < 8; i++)
#pragma unroll
        for (int j = 0; j < 8; j++) acc[i][j] = 0.f;

#pragma unroll
    for (int hb = 0; hb < 2; hb++) {
        // cooperative stage of B[hb*64 .. +64][0..128] (contiguous 32KB)
        {
            const float4* src = (const float4*)(Bm + hb * 64 * HID);
            float4* dst = (float4*)Bs;
#pragma unroll
            for (int j = 0; j < 8; j++) dst[t + j * 256] = src[t + j * 256];
        }
        __syncthreads();

        for (int h4 = 0; h4 < 16; h4++) {
            int h = hb * 64 + h4 * 4;
            float4 av[8];
#pragma unroll
            for (int i = 0; i < 8; i++)
                av[i] = *(const float4*)&A[(size_t)(r0 + i) * HID + h];
#pragma unroll
            for (int u = 0; u < 4; u++) {
                float4 b0 = *(const float4*)&Bs[(h4 * 4 + u) * 128 + c0];
                float4 b1 = *(const float4*)&Bs[(h4 * 4 + u) * 128 + c0 + 64];
#pragma unroll
                for (int i = 0; i < 8; i++) {
                    float a = (u == 0) ? av[i].x : (u == 1) ? av[i].y : (u == 2) ? av[i].z : av[i].w;
                    acc[i][0] += a * b0.x; acc[i][1] += a * b0.y;
                    acc[i][2] += a * b0.z; acc[i][3] += a * b0.w;
                    acc[i][4] += a * b1.x; acc[i][5] += a * b1.y;
                    acc[i][6] += a * b1.z; acc[i][7] += a * b1.w;
                }
            }
        }
        __syncthreads();
    }

    // epilogue: bias + store (guarded) + optional att dots
    float4 bs0 = {0, 0, 0, 0}, bs1 = {0, 0, 0, 0};
    if (bias) {
        bs0 = *(const float4*)&bias[c0];
        bs1 = *(const float4*)&bias[c0 + 64];
    }
#pragma unroll
    for (int i = 0; i < 8; i++) {
        int m = r0 + i;
        if (m < M) {
            float4 w0, w1;
            w0.x = acc[i][0] + bs0.x; w0.y = acc[i][1] + bs0.y;
            w0.z = acc[i][2] + bs0.z; w0.w = acc[i][3] + bs0.w;
            w1.x = acc[i][4] + bs1.x; w1.y = acc[i][5] + bs1.y;
            w1.z = acc[i][6] + bs1.z; w1.w = acc[i][7] + bs1.w;
            *(float4*)&C[(size_t)m * HID + c0] = w0;
            *(float4*)&C[(size_t)m * HID + c0 + 64] = w1;
        }
    }

    if (atts) {
        float4 sa0 = *(const float4*)&atts[c0];
        float4 sa1 = *(const float4*)&atts[c0 + 64];
        float4 da0 = *(const float4*)&attd[c0];
        float4 da1 = *(const float4*)&attd[c0 + 64];
#pragma unroll
        for (int i = 0; i < 8; i++) {
            float ps = acc[i][0] * sa0.x + acc[i][1] * sa0.y + acc[i][2] * sa0.z + acc[i][3] * sa0.w
                     + acc[i][4] * sa1.x + acc[i][5] * sa1.y + acc[i][6] * sa1.z + acc[i][7] * sa1.w;
            float pd = acc[i][0] * da0.x + acc[i][1] * da0.y + acc[i][2] * da0.z + acc[i][3] * da0.w
                     + acc[i][4] * da1.x + acc[i][5] * da1.y + acc[i][6] * da1.z + acc[i][7] * da1.w;
            // reduce across the 16 tc lanes (lanes [0..15] / [16..31] are distinct tr)
            for (int o = 8; o; o >>= 1) {
                ps += __shfl_down_sync(0xffffffffu, ps, o, 16);
                pd += __shfl_down_sync(0xffffffffu, pd, o, 16);
            }
            int m = r0 + i;
            if (tc == 0 && m < M) { g_as[m] = ps; g_ad[m] = pd; }
        }
    }
}

// 32-row list-indirected GEMM: rows from g_list2 (0) / g_list3 (1)
__global__ void __launch_bounds__(256) k_gemml(int lsel, const float* __restrict__ Bm,
                                               const float* __restrict__ atts,
                                               const float* __restrict__ attd) {
    int cnt = lsel ? g_cnt3 : g_cnt2;
    if (blockIdx.x * 32 >= cnt) return;
    const int* list = lsel ? g_list3 : g_list2;

    int t = threadIdx.x;
    int rg = t >> 3, cg = t & 7;
    int m = blockIdx.x * 32 + rg;
    int k0 = cg * 16;

    bool ok = m < cnt;
    int row = ok ? list[m] : list[0];

    float acc[16];
#pragma unroll
    for (int j = 0; j < 16; j++) acc[j] = 0.f;

    for (int h = 0; h < HID; h += 4) {
        float4 v = *(const float4*)&g_nodes[(size_t)row * HID + h];
        float a[4] = {v.x, v.y, v.z, v.w};
#pragma unroll
        for (int u = 0; u < 4; u++) {
            float br[16];
#pragma unroll
            for (int q = 0; q < 4; q++) {
                float4 w = *(const float4*)&Bm[(size_t)(h + u) * HID + k0 + q * 4];
                br[q * 4 + 0] = w.x; br[q * 4 + 1] = w.y;
                br[q * 4 + 2] = w.z; br[q * 4 + 3] = w.w;
            }
            float av = a[u];
#pragma unroll
            for (int j = 0; j < 16; j++) acc[j] += av * br[j];
        }
    }

    if (ok) {
#pragma unroll
        for (int q = 0; q < 4; q++) {
            float4 w;
            w.x = acc[q * 4 + 0]; w.y = acc[q * 4 + 1];
            w.z = acc[q * 4 + 2]; w.w = acc[q * 4 + 3];
            *(float4*)&g_xl[(size_t)row * HID + k0 + q * 4] = w;
        }
    }

    float ps = 0.f, pd = 0.f;
#pragma unroll
    for (int q = 0; q < 4; q++) {
        float4 w = *(const float4*)&atts[k0 + q * 4];
        float4 u = *(const float4*)&attd[k0 + q * 4];
        ps += acc[q * 4 + 0] * w.x + acc[q * 4 + 1] * w.y + acc[q * 4 + 2] * w.z + acc[q * 4 + 3] * w.w;
        pd += acc[q * 4 + 0] * u.x + acc[q * 4 + 1] * u.y + acc[q * 4 + 2] * u.z + acc[q * 4 + 3] * u.w;
    }
    for (int o = 4; o; o >>= 1) {
        ps += __shfl_down_sync(0xffffffffu, ps, o, 8);
        pd += __shfl_down_sync(0xffffffffu, pd, o, 8);
    }
    if (cg == 0 && ok) { g_as[row] = ps; g_ad[row] = pd; }
}

// restricted softmax-aggregation: dst from list (0=list2, 1=list3, 2=ctx[+out])
__global__ void k_hopl(int lsel, const float* __restrict__ gbias,
                       float* __restrict__ out) {
    int wi = (blockIdx.x * blockDim.x + threadIdx.x) >> 5;
    int lane = threadIdx.x & 31;
    int cnt = (lsel == 0) ? g_cnt2 : (lsel == 1) ? g_cnt3 : Bq;
    if (wi >= cnt) return;
    int w = (lsel == 0) ? g_list2[wi] : (lsel == 1) ? g_list3[wi] : g_ctxn[wi];

    int s = g_off[w], e = g_off[w + 1];
    float adn = g_ad[w];
    float aself = g_as[w] + adn + g_loop[w];
    aself = aself >= 0.f ? aself : 0.2f * aself;
    float m = aself;
    for (int i = s + lane; i < e; i += 32) {
        float a = g_as[g_csrc[i]] + adn + g_cae[i];
        a = a >= 0.f ? a : 0.2f * a;
        m = fmaxf(m, a);
    }
    for (int o = 16; o; o >>= 1) m = fmaxf(m, __shfl_xor_sync(0xffffffffu, m, o));

    float eself = __expf(aself - m);
    float s_sum = eself;
    float4 v = ((const float4*)&g_xl[(size_t)w * HID])[lane];
    float4 acc;
    acc.x = eself * v.x; acc.y = eself * v.y; acc.z = eself * v.z; acc.w = eself * v.w;

    for (int i = s; i < e; i++) {
        int src = g_csrc[i];
        float a = g_as[src] + adn + g_cae[i];
        a = a >= 0.f ? a : 0.2f * a;
        float ee = __expf(a - m);
        s_sum += ee;
        float4 u = ((const float4*)&g_xl[(size_t)src * HID])[lane];
        acc.x += ee * u.x; acc.y += ee * u.y; acc.z += ee * u.z; acc.w += ee * u.w;
    }
    float inv = 1.f / s_sum;
    float4 bb = ((const float4*)gbias)[lane];
    float4 o;
    o.x = acc.x * inv + bb.x; o.y = acc.y * inv + bb.y;
    o.z = acc.z * inv + bb.z; o.w = acc.w * inv + bb.w;
    ((float4*)&g_nodes[(size_t)w * HID])[lane] = o;
    if (lsel == 2) ((float4*)&out[(size_t)wi * HID])[lane] = o;
}

extern "C" void kernel_launch(void* const* d_in, const int* in_sizes, int n_in,
                              void* d_out, int out_size) {
    const float* lm    = (const float*)d_in[0];
    const float* ne    = (const float*)d_in[1];
    const void*  ei    = d_in[2];
    const void*  et    = d_in[3];
    const void*  ctxn  = d_in[4];
    const float* Wlm  = (const float*)d_in[5];
    const float* blm  = (const float*)d_in[6];
    const float* Wbil = (const float*)d_in[7];
    const float* bbil = (const float*)d_in[8];
    const float* tab  = (const float*)d_in[9];
    const float* Wgat = (const float*)d_in[10];
    const float* atts = (const float*)d_in[11];
    const float* attd = (const float*)d_in[12];
    const float* Wed  = (const float*)d_in[13];
    const float* atte = (const float*)d_in[14];
    const float* gb   = (const float*)d_in[15];
    float* out = (float*)d_out;

    int E = in_sizes[2] / 2;
    int eb = (E + 255) / 256;
    int nb128 = (NN + 127) / 128;
    int nb32  = (NN + 31) / 32;
    int wb = (NN + 7) / 8;

    k_init<<<1024, 256>>>(ne);
    k_cvt<<<eb, 256>>>(ei, et, ctxn, E);      // cvt + deg + ctx marks
    k_prep<<<1, 128>>>(Wed, atte, tab);       // before k_fill (g_tdot)
    k_mark3<<<eb, 256>>>(E);
    k_scan<<<1, 1024>>>();
    k_mark2<<<eb, 256>>>(E);
    k_fill<<<eb, 256>>>(E);
    k_compact<<<(NN + 255) / 256, 256>>>();
    k_loopdot<<<wb, 256>>>();

    k_ctx<<<Bq, 1024>>>(lm, Wlm, blm);
    k_tmp<<<HID, 256>>>(lm, Wbil);

    // nodes0: per-graph  xg @ tmp[b]^T + b_bil
    dim3 g0((NPG + 127) / 128, Bq);
    k_gemm2<<<g0, 256>>>(0, nullptr, NPG, NPG * HID, bbil, nullptr, nullptr);

    // hop 1: full GEMM (a_src needed everywhere), aggregate at A2
    k_gemm2<<<dim3(nb128, 1), 256>>>(1, Wgat, NN, 0, nullptr, atts, attd);
    k_hopl<<<wb, 256>>>(0, gb, nullptr);

    // hop 2: GEMM over A2, aggregate at A3
    k_gemml<<<nb32, 256>>>(0, Wgat, atts, attd);
    k_hopl<<<wb, 256>>>(1, gb, nullptr);

    // hop 3: GEMM over A3, aggregate at ctx (+ output)
    k_gemml<<<nb32, 256>>>(1, Wgat, atts, attd);
    k_hopl<<<(Bq + 7) / 8, 256>>>(2, gb, out);
}